// round 5
// baseline (speedup 1.0000x reference)
#include <cuda_runtime.h>
#include <cstdint>
#include <cstddef>

// BioConvolution: 256 independent GEMMs  C_l[64,128] = A_l[64,1024] * B_l[1024,128]
//   A_l[m][k] = X[m, r*4+i, c*4+j, ch]  (k = i*256+j*64+ch, l = r*16+c)
//   B_l[k][f] = filters[l*131072 + k*128 + f]
//   out[(m*256+l)*128+f] = relu(C + bias[f])
//
// fp16 mma.m16n8k16 + ldmatrix (sm_80-portable PTX). Convert-once on load,
// but with the cvt DEFERRED: raw float4 LDGs land in a register buffer and
// are only packed at STS time, one full compute-chunk later, so DRAM latency
// is hidden behind MMA work (round 4's failure was LDG->cvt back-to-back).

namespace {

constexpr int NST = 16;           // K chunks of 64
constexpr int AH  = 72;           // A smem stride (halves)
constexpr int BH  = 136;          // B smem stride (halves)
constexpr int TA  = 64 * AH;
constexpr int STG = TA + 64 * BH; // halves per stage
constexpr int SMEM_BYTES = 2 * STG * 2;  // 53248 B

__device__ __forceinline__ uint32_t smem_u32(const void* p) {
    return static_cast<uint32_t>(__cvta_generic_to_shared(p));
}
__device__ __forceinline__ uint32_t pack_h2(float lo, float hi) {
    uint32_t d;
    asm("cvt.rn.f16x2.f32 %0, %1, %2;" : "=r"(d) : "f"(hi), "f"(lo));
    return d;
}
__device__ __forceinline__ void sts128(uint32_t a, uint32_t x, uint32_t y,
                                       uint32_t z, uint32_t w) {
    asm volatile("st.shared.v4.b32 [%0], {%1,%2,%3,%4};"
                 :: "r"(a), "r"(x), "r"(y), "r"(z), "r"(w));
}
__device__ __forceinline__ void ldmx4(uint32_t* r, uint32_t a) {
    asm volatile("ldmatrix.sync.aligned.m8n8.x4.shared.b16 {%0,%1,%2,%3}, [%4];"
                 : "=r"(r[0]), "=r"(r[1]), "=r"(r[2]), "=r"(r[3]) : "r"(a));
}
__device__ __forceinline__ void ldmx4t(uint32_t* r, uint32_t a) {
    asm volatile("ldmatrix.sync.aligned.m8n8.x4.trans.shared.b16 {%0,%1,%2,%3}, [%4];"
                 : "=r"(r[0]), "=r"(r[1]), "=r"(r[2]), "=r"(r[3]) : "r"(a));
}
__device__ __forceinline__ void mma_f16(float* c, const uint32_t* a, const uint32_t* b) {
    asm volatile(
        "mma.sync.aligned.m16n8k16.row.col.f32.f16.f16.f32 "
        "{%0,%1,%2,%3}, {%4,%5,%6,%7}, {%8,%9}, {%0,%1,%2,%3};"
        : "+f"(c[0]), "+f"(c[1]), "+f"(c[2]), "+f"(c[3])
        : "r"(a[0]), "r"(a[1]), "r"(a[2]), "r"(a[3]), "r"(b[0]), "r"(b[1]));
}

__global__ __launch_bounds__(256, 2)
void bioconv_f16p_kernel(const float* __restrict__ X,
                         const float* __restrict__ filt,
                         const float* __restrict__ bias,
                         float* __restrict__ out) {
    extern __shared__ __align__(16) char smem[];
    const uint32_t sb = smem_u32(smem);

    const int tid = threadIdx.x;
    const int l   = blockIdx.x;
    const int r   = l >> 4;
    const int cc  = l & 15;

    // ---- loader mapping ----
    const int am = tid >> 2, aq = tid & 3;   // A: row am, 16 floats at aq*16
    const int bk = tid & 63, bq = tid >> 6;  // B: k-row bk, 32 floats at bq*32
    const float* gA0 = X + (size_t)am * 262144 + r * 16384 + cc * 256 + aq * 16;
    const float* gB0 = filt + (size_t)l * 131072 + (size_t)bk * 128 + bq * 32;

    const uint32_t a_sts = (am * AH + aq * 16) * 2;
    const uint32_t b_sts = TA * 2 + (bk * BH + bq * 32) * 2;

    // ---- compute mapping: 8 warps, 2(M) x 4(N), warp tile 32x32 ----
    const int lane = tid & 31;
    const int wid  = tid >> 5;
    const int wm   = wid >> 2;
    const int wn   = wid & 3;
    const int g    = lane >> 2;
    const int t4   = lane & 3;

    const uint32_t a_off = ((wm * 32 + (lane & 15)) * AH + (lane >> 4) * 8) * 2;
    const uint32_t b_off = TA * 2 +
        ((lane & 15) * BH + wn * 32 + ((lane >> 4) & 1) * 8) * 2;

    float acc[2][4][4];
#pragma unroll
    for (int i = 0; i < 2; ++i)
#pragma unroll
        for (int j = 0; j < 4; ++j)
#pragma unroll
            for (int k = 0; k < 4; ++k) acc[i][j][k] = 0.f;

    float4 fb[12];  // raw chunk buffer: 4 x A-float4, 8 x B-float4

    auto ldg_chunk = [&](int t) {
        const float* ga = gA0 + (t >> 2) * 4096 + (t & 3) * 64;
#pragma unroll
        for (int i = 0; i < 4; ++i)
            fb[i] = *reinterpret_cast<const float4*>(ga + i * 4);
        const float* gb = gB0 + (size_t)t * 8192;
#pragma unroll
        for (int i = 0; i < 8; ++i)
            fb[4 + i] = *reinterpret_cast<const float4*>(gb + i * 4);
    };
    auto cvt_sts = [&](int s) {  // pack fb -> halves, store to stage s
        const uint32_t base = sb + s * (STG * 2);
        uint32_t h[8];
#pragma unroll
        for (int i = 0; i < 4; ++i) {
            h[i * 2]     = pack_h2(fb[i].x, fb[i].y);
            h[i * 2 + 1] = pack_h2(fb[i].z, fb[i].w);
        }
        sts128(base + a_sts,      h[0], h[1], h[2], h[3]);
        sts128(base + a_sts + 16, h[4], h[5], h[6], h[7]);
#pragma unroll
        for (int i = 0; i < 4; ++i) {
            const uint32_t p0 = pack_h2(fb[4 + i * 2].x, fb[4 + i * 2].y);
            const uint32_t p1 = pack_h2(fb[4 + i * 2].z, fb[4 + i * 2].w);
            const uint32_t p2 = pack_h2(fb[5 + i * 2].x, fb[5 + i * 2].y);
            const uint32_t p3 = pack_h2(fb[5 + i * 2].z, fb[5 + i * 2].w);
            sts128(base + b_sts + i * 16, p0, p1, p2, p3);
        }
    };

    // prologue: stages 0 and 1 filled, chunk 2 raw in registers
    ldg_chunk(0); cvt_sts(0);
    ldg_chunk(1); cvt_sts(1);
    ldg_chunk(2);
    __syncthreads();

    for (int t = 0; t < NST; ++t) {
        const uint32_t base = sb + (t & 1) * (STG * 2);
        const uint32_t aa = base + a_off;
        const uint32_t bb = base + b_off;

#pragma unroll
        for (int kh = 0; kh < 4; ++kh) {
            uint32_t A0[4], A1[4], B0[4], B1[4];
            ldmx4(A0, aa + kh * 32);
            ldmx4(A1, aa + 16 * AH * 2 + kh * 32);
            ldmx4t(B0, bb + kh * (16 * BH * 2));
            ldmx4t(B1, bb + 32 + kh * (16 * BH * 2));

            mma_f16(acc[0][0], A0, &B0[0]);
            mma_f16(acc[0][1], A0, &B0[2]);
            mma_f16(acc[0][2], A0, &B1[0]);
            mma_f16(acc[0][3], A0, &B1[2]);
            mma_f16(acc[1][0], A1, &B0[0]);
            mma_f16(acc[1][1], A1, &B0[2]);
            mma_f16(acc[1][2], A1, &B1[0]);
            mma_f16(acc[1][3], A1, &B1[2]);
        }

        if (t + 2 < NST) {
            __syncthreads();          // all warps done reading stage t&1
            cvt_sts(t & 1);           // write chunk t+2 (in fb) into stage t&1
            if (t + 3 < NST) ldg_chunk(t + 3);  // consumed after compute(t+1)
            __syncthreads();          // STS(t+2) visible before anyone computes on it
        }
    }

    // ---- epilogue: bias + relu ----
#pragma unroll
    for (int nt = 0; nt < 4; ++nt) {
        const int n0 = wn * 32 + nt * 8 + t4 * 2;
        const float2 bv = *reinterpret_cast<const float2*>(bias + n0);
#pragma unroll
        for (int mt = 0; mt < 2; ++mt) {
            const int m = wm * 32 + mt * 16 + g;
            float2 o0, o1;
            o0.x = fmaxf(acc[mt][nt][0] + bv.x, 0.f);
            o0.y = fmaxf(acc[mt][nt][1] + bv.y, 0.f);
            o1.x = fmaxf(acc[mt][nt][2] + bv.x, 0.f);
            o1.y = fmaxf(acc[mt][nt][3] + bv.y, 0.f);
            *reinterpret_cast<float2*>(out + ((size_t)m * 256 + l) * 128 + n0) = o0;
            *reinterpret_cast<float2*>(out + ((size_t)(m + 8) * 256 + l) * 128 + n0) = o1;
        }
    }
}

}  // namespace

extern "C" void kernel_launch(void* const* d_in, const int* in_sizes, int n_in,
                              void* d_out, int out_size) {
    const float* X    = (const float*)d_in[0];
    const float* filt = (const float*)d_in[1];
    const float* bias = (const float*)d_in[2];
    float* out        = (float*)d_out;

    cudaFuncSetAttribute(bioconv_f16p_kernel,
                         cudaFuncAttributeMaxDynamicSharedMemorySize, SMEM_BYTES);
    bioconv_f16p_kernel<<<256, 256, SMEM_BYTES>>>(X, filt, bias, out);
}

// round 6
// speedup vs baseline: 1.5861x; 1.5861x over previous
#include <cuda_runtime.h>
#include <cstdint>
#include <cstddef>

// BioConvolution: 256 independent GEMMs  C_l[64,128] = A_l[64,1024] * B_l[1024,128]
//   A_l[m][k] = X[m, r*4+i, c*4+j, ch]  (k = i*256+j*64+ch, l = r*16+c)
//   B_l[k][f] = filters[l*131072 + k*128 + f]
//   out[(m*256+l)*128+f] = relu(C + bias[f])
//
// fp16 mma.m16n8k16 + ldmatrix (sm_80-portable PTX), convert-once-on-load with
// deferred cvt. Rounds 4/5 regressed because the loader was uncoalesced
// (B lanes 512B apart -> 32 lines/LDG). This round: lane-contiguous loads
// (4 lines/LDG for both A and B), STS.64 of packed halves. Compute side
// (ldmatrix addressing, MMA, epilogue) is byte-identical to the verified code.

namespace {

constexpr int NST = 16;           // K chunks of 64
constexpr int AH  = 72;           // A smem stride (halves) = 144B
constexpr int BH  = 136;          // B smem stride (halves) = 272B
constexpr int TA  = 64 * AH;
constexpr int STG = TA + 64 * BH; // halves per stage
constexpr int SMEM_BYTES = 2 * STG * 2;  // 53248 B

__device__ __forceinline__ uint32_t smem_u32(const void* p) {
    return static_cast<uint32_t>(__cvta_generic_to_shared(p));
}
__device__ __forceinline__ uint32_t pack_h2(float lo, float hi) {
    uint32_t d;
    asm("cvt.rn.f16x2.f32 %0, %1, %2;" : "=r"(d) : "f"(hi), "f"(lo));
    return d;
}
__device__ __forceinline__ void sts64(uint32_t a, uint32_t x, uint32_t y) {
    asm volatile("st.shared.v2.b32 [%0], {%1,%2};" :: "r"(a), "r"(x), "r"(y));
}
__device__ __forceinline__ void ldmx4(uint32_t* r, uint32_t a) {
    asm volatile("ldmatrix.sync.aligned.m8n8.x4.shared.b16 {%0,%1,%2,%3}, [%4];"
                 : "=r"(r[0]), "=r"(r[1]), "=r"(r[2]), "=r"(r[3]) : "r"(a));
}
__device__ __forceinline__ void ldmx4t(uint32_t* r, uint32_t a) {
    asm volatile("ldmatrix.sync.aligned.m8n8.x4.trans.shared.b16 {%0,%1,%2,%3}, [%4];"
                 : "=r"(r[0]), "=r"(r[1]), "=r"(r[2]), "=r"(r[3]) : "r"(a));
}
__device__ __forceinline__ void mma_f16(float* c, const uint32_t* a, const uint32_t* b) {
    asm volatile(
        "mma.sync.aligned.m16n8k16.row.col.f32.f16.f16.f32 "
        "{%0,%1,%2,%3}, {%4,%5,%6,%7}, {%8,%9}, {%0,%1,%2,%3};"
        : "+f"(c[0]), "+f"(c[1]), "+f"(c[2]), "+f"(c[3])
        : "r"(a[0]), "r"(a[1]), "r"(a[2]), "r"(a[3]), "r"(b[0]), "r"(b[1]));
}

__global__ __launch_bounds__(256, 2)
void bioconv_f16c_kernel(const float* __restrict__ X,
                         const float* __restrict__ filt,
                         const float* __restrict__ bias,
                         float* __restrict__ out) {
    extern __shared__ __align__(16) char smem[];
    const uint32_t sb = smem_u32(smem);

    const int tid = threadIdx.x;
    const int l   = blockIdx.x;
    const int r   = l >> 4;
    const int cc  = l & 15;

    // ---- coalesced loader mapping ----
    // A chunk: 64 rows x 64 floats = 1024 f4; thread v-th f4: row v*16+(tid>>4),
    // col tid&15. Warp covers 2 full 256B rows per LDG (4 lines).
    const int ar = tid >> 4, ac = tid & 15;
    // B chunk: 64 rows x 128 floats = 2048 f4; thread v-th f4: row v*8+(tid>>5),
    // col tid&31. Warp covers 2 full 512B rows per LDG (4 lines).
    const int br = tid >> 5, bc = tid & 31;

    const float* gA0 = X + (size_t)ar * 262144 + r * 16384 + cc * 256 + ac * 4;
    const float* gB0 = filt + (size_t)l * 131072 + (size_t)br * 128 + bc * 4;

    const uint32_t a_sts = (uint32_t)(ar * AH + ac * 4) * 2;            // bytes
    const uint32_t b_sts = (uint32_t)TA * 2 + (uint32_t)(br * BH + bc * 4) * 2;

    // ---- compute mapping: 8 warps, 2(M) x 4(N), warp tile 32x32 (verified) ----
    const int lane = tid & 31;
    const int wid  = tid >> 5;
    const int wm   = wid >> 2;
    const int wn   = wid & 3;
    const int g    = lane >> 2;
    const int t4   = lane & 3;

    const uint32_t a_off = ((wm * 32 + (lane & 15)) * AH + (lane >> 4) * 8) * 2;
    const uint32_t b_off = TA * 2 +
        ((lane & 15) * BH + wn * 32 + ((lane >> 4) & 1) * 8) * 2;

    float acc[2][4][4];
#pragma unroll
    for (int i = 0; i < 2; ++i)
#pragma unroll
        for (int j = 0; j < 4; ++j)
#pragma unroll
            for (int k = 0; k < 4; ++k) acc[i][j][k] = 0.f;

    float4 fb[12];  // raw chunk: 4 A-f4 + 8 B-f4

    auto ldg_chunk = [&](int t) {
        const float* ga = gA0 + (t >> 2) * 4096 + (t & 3) * 64;
#pragma unroll
        for (int v = 0; v < 4; ++v)
            fb[v] = *reinterpret_cast<const float4*>(ga + (size_t)v * 16 * 262144);
        const float* gb = gB0 + (size_t)t * 8192;
#pragma unroll
        for (int v = 0; v < 8; ++v)
            fb[4 + v] = *reinterpret_cast<const float4*>(gb + v * 1024);
    };
    auto cvt_sts = [&](int s) {
        const uint32_t base = sb + s * (STG * 2);
#pragma unroll
        for (int v = 0; v < 4; ++v)
            sts64(base + a_sts + v * 16 * (AH * 2),
                  pack_h2(fb[v].x, fb[v].y), pack_h2(fb[v].z, fb[v].w));
#pragma unroll
        for (int v = 0; v < 8; ++v)
            sts64(base + b_sts + v * 8 * (BH * 2),
                  pack_h2(fb[4 + v].x, fb[4 + v].y),
                  pack_h2(fb[4 + v].z, fb[4 + v].w));
    };

    // prologue: stages 0,1 filled; chunk 2 raw in registers
    ldg_chunk(0); cvt_sts(0);
    ldg_chunk(1); cvt_sts(1);
    ldg_chunk(2);
    __syncthreads();

    for (int t = 0; t < NST; ++t) {
        const uint32_t base = sb + (t & 1) * (STG * 2);
        const uint32_t aa = base + a_off;
        const uint32_t bb = base + b_off;

#pragma unroll
        for (int kh = 0; kh < 4; ++kh) {
            uint32_t A0[4], A1[4], B0[4], B1[4];
            ldmx4(A0, aa + kh * 32);
            ldmx4(A1, aa + 16 * AH * 2 + kh * 32);
            ldmx4t(B0, bb + kh * (16 * BH * 2));
            ldmx4t(B1, bb + 32 + kh * (16 * BH * 2));

            mma_f16(acc[0][0], A0, &B0[0]);
            mma_f16(acc[0][1], A0, &B0[2]);
            mma_f16(acc[0][2], A0, &B1[0]);
            mma_f16(acc[0][3], A0, &B1[2]);
            mma_f16(acc[1][0], A1, &B0[0]);
            mma_f16(acc[1][1], A1, &B0[2]);
            mma_f16(acc[1][2], A1, &B1[0]);
            mma_f16(acc[1][3], A1, &B1[2]);
        }

        if (t + 2 < NST) {
            __syncthreads();          // stage t&1 fully consumed
            cvt_sts(t & 1);           // chunk t+2 -> stage t&1
            if (t + 3 < NST) ldg_chunk(t + 3);
            __syncthreads();          // chunk t+2 visible
        }
    }

    // ---- epilogue: bias + relu ----
#pragma unroll
    for (int nt = 0; nt < 4; ++nt) {
        const int n0 = wn * 32 + nt * 8 + t4 * 2;
        const float2 bv = *reinterpret_cast<const float2*>(bias + n0);
#pragma unroll
        for (int mt = 0; mt < 2; ++mt) {
            const int m = wm * 32 + mt * 16 + g;
            float2 o0, o1;
            o0.x = fmaxf(acc[mt][nt][0] + bv.x, 0.f);
            o0.y = fmaxf(acc[mt][nt][1] + bv.y, 0.f);
            o1.x = fmaxf(acc[mt][nt][2] + bv.x, 0.f);
            o1.y = fmaxf(acc[mt][nt][3] + bv.y, 0.f);
            *reinterpret_cast<float2*>(out + ((size_t)m * 256 + l) * 128 + n0) = o0;
            *reinterpret_cast<float2*>(out + ((size_t)(m + 8) * 256 + l) * 128 + n0) = o1;
        }
    }
}

}  // namespace

extern "C" void kernel_launch(void* const* d_in, const int* in_sizes, int n_in,
                              void* d_out, int out_size) {
    const float* X    = (const float*)d_in[0];
    const float* filt = (const float*)d_in[1];
    const float* bias = (const float*)d_in[2];
    float* out        = (float*)d_out;

    cudaFuncSetAttribute(bioconv_f16c_kernel,
                         cudaFuncAttributeMaxDynamicSharedMemorySize, SMEM_BYTES);
    bioconv_f16c_kernel<<<256, 256, SMEM_BYTES>>>(X, filt, bias, out);
}